// round 7
// baseline (speedup 1.0000x reference)
#include <cuda_runtime.h>
#include <cstdint>

#define N_NODES   100000
#define N_EDGES   1600000
#define IN_FEATS  64
#define OUT_FEATS 32
#define NODE_PAIRS (N_NODES / 2)

// Scratch (no cudaMalloc allowed)
__device__ float g_hW[N_NODES * OUT_FEATS];   // 12.8 MB
__device__ float g_deg[N_NODES];              // 0.4 MB

// ---------------------------------------------------------------------------
// f32x2 helpers
// ---------------------------------------------------------------------------
__device__ __forceinline__ unsigned long long pack2(float lo, float hi) {
    unsigned long long r;
    asm("mov.b64 %0, {%1, %2};" : "=l"(r) : "f"(lo), "f"(hi));
    return r;
}
__device__ __forceinline__ void fma2(unsigned long long& d,
                                     unsigned long long a,
                                     unsigned long long b) {
    asm("fma.rn.f32x2 %0, %1, %2, %0;" : "+l"(d) : "l"(a), "l"(b));
}
__device__ __forceinline__ float unpack_add(unsigned long long v) {
    float lo, hi;
    asm("mov.b64 {%0, %1}, %2;" : "=f"(lo), "=f"(hi) : "l"(v));
    return lo + hi;
}
__device__ __forceinline__ void lds_v2b64(unsigned long long& a,
                                          unsigned long long& b,
                                          unsigned int addr) {
    asm volatile("ld.shared.v2.b64 {%0, %1}, [%2];"
                 : "=l"(a), "=l"(b) : "r"(addr));
}
__device__ __forceinline__ unsigned int smem_addr_u32(const void* p) {
    unsigned int a;
    asm("{ .reg .u64 t; cvta.to.shared.u64 t, %1; cvt.u32.u64 %0, t; }"
        : "=r"(a) : "l"(p));
    return a;
}

// ---------------------------------------------------------------------------
// Kernel 1: fused  (a) zero d_out + g_deg,  (b) hW = h @ W  via fma.rn.f32x2
// 2-node x 8-feature tile per thread (round-5 shape), inner product paired
// over k. W in smem k-pair-interleaved: sWp[k2*32+j] = (W[2k2][j], W[2k2+1][j]).
// ---------------------------------------------------------------------------
__global__ void __launch_bounds__(256) gemm_zero_kernel(
        const float* __restrict__ h,
        const float* __restrict__ W,
        float*       __restrict__ out) {
    __shared__ float2 sWp[(IN_FEATS / 2) * OUT_FEATS];   // 32 x 32 pairs, 8 KB

    // stage W pair-interleaved
    for (int i = threadIdx.x; i < (IN_FEATS / 2) * OUT_FEATS; i += blockDim.x) {
        int k2 = i >> 5;     // pair index
        int j  = i & 31;     // output feature
        float a = __ldg(W + (2 * k2)     * OUT_FEATS + j);
        float c = __ldg(W + (2 * k2 + 1) * OUT_FEATS + j);
        sWp[i] = make_float2(a, c);
    }

    // grid-stride zero of out (float4) and g_deg
    {
        int tg     = blockIdx.x * blockDim.x + threadIdx.x;
        int stride = gridDim.x * blockDim.x;
        float4 z = make_float4(0.f, 0.f, 0.f, 0.f);
        float4* out4 = reinterpret_cast<float4*>(out);
        for (int i = tg; i < N_NODES * OUT_FEATS / 4; i += stride)
            out4[i] = z;
        for (int i = tg; i < N_NODES; i += stride)
            g_deg[i] = 0.0f;
    }
    __syncthreads();

    int t  = blockIdx.x * blockDim.x + threadIdx.x;
    int np = t >> 2;            // node pair
    int jg = t & 3;             // 8-feature group
    if (np >= NODE_PAIRS) return;

    int node0 = np * 2;
    const float* hbase = h + (size_t)node0 * IN_FEATS;

    // byte offset of this thread's j-group within a k2 row (32 pairs * 8B row)
    unsigned int wbase = smem_addr_u32(sWp) + (unsigned)jg * 8 * 8;

    // acc2[i][jj]: packed (even-k sum, odd-k sum) for node i, feature jg*8+jj
    unsigned long long acc2[2][8];
    #pragma unroll
    for (int i = 0; i < 2; i++)
        #pragma unroll
        for (int j = 0; j < 8; j++) acc2[i][j] = 0ull;

    #pragma unroll 4
    for (int k4 = 0; k4 < IN_FEATS / 4; k4++) {
        float4 hv0 = __ldg(reinterpret_cast<const float4*>(hbase + k4 * 4));
        float4 hv1 = __ldg(reinterpret_cast<const float4*>(hbase + IN_FEATS + k4 * 4));

        #pragma unroll
        for (int p = 0; p < 2; p++) {      // two k2 per k4
            int k2 = k4 * 2 + p;
            unsigned long long hp0 = (p == 0) ? pack2(hv0.x, hv0.y) : pack2(hv0.z, hv0.w);
            unsigned long long hp1 = (p == 0) ? pack2(hv1.x, hv1.y) : pack2(hv1.z, hv1.w);

            unsigned int ka = wbase + (unsigned)k2 * (OUT_FEATS * 8);
            unsigned long long w0, w1, w2, w3, w4, w5, w6, w7;
            lds_v2b64(w0, w1, ka);
            lds_v2b64(w2, w3, ka + 16);
            lds_v2b64(w4, w5, ka + 32);
            lds_v2b64(w6, w7, ka + 48);

            fma2(acc2[0][0], hp0, w0); fma2(acc2[0][1], hp0, w1);
            fma2(acc2[0][2], hp0, w2); fma2(acc2[0][3], hp0, w3);
            fma2(acc2[0][4], hp0, w4); fma2(acc2[0][5], hp0, w5);
            fma2(acc2[0][6], hp0, w6); fma2(acc2[0][7], hp0, w7);

            fma2(acc2[1][0], hp1, w0); fma2(acc2[1][1], hp1, w1);
            fma2(acc2[1][2], hp1, w2); fma2(acc2[1][3], hp1, w3);
            fma2(acc2[1][4], hp1, w4); fma2(acc2[1][5], hp1, w5);
            fma2(acc2[1][6], hp1, w6); fma2(acc2[1][7], hp1, w7);
        }
    }

    #pragma unroll
    for (int i = 0; i < 2; i++) {
        float r[8];
        #pragma unroll
        for (int jj = 0; jj < 8; jj++) r[jj] = unpack_add(acc2[i][jj]);
        float4* orow = reinterpret_cast<float4*>(
            g_hW + (size_t)(node0 + i) * OUT_FEATS + jg * 8);
        orow[0] = make_float4(r[0], r[1], r[2], r[3]);
        orow[1] = make_float4(r[4], r[5], r[6], r[7]);
    }
}

// ---------------------------------------------------------------------------
// Kernel 2: edge scatter. 8 threads per edge, one red.global.add.v4.f32 each.
// ---------------------------------------------------------------------------
__global__ void __launch_bounds__(256) scatter_kernel(
        const int*   __restrict__ src,
        const int*   __restrict__ dst,
        const float* __restrict__ order,
        float*       __restrict__ agg) {
    int t   = blockIdx.x * blockDim.x + threadIdx.x;
    int e   = t >> 3;
    int sub = t & 7;
    if (e >= N_EDGES) return;

    int   s = __ldg(src + e);
    int   d = __ldg(dst + e);
    float w = __ldg(order + e);

    float4 v = __ldg(reinterpret_cast<const float4*>(
                         g_hW + (size_t)s * OUT_FEATS + sub * 4));
    v.x *= w; v.y *= w; v.z *= w; v.w *= w;

    float* a = agg + (size_t)d * OUT_FEATS + sub * 4;
    asm volatile("red.global.add.v4.f32 [%0], {%1, %2, %3, %4};"
                 :: "l"(a), "f"(v.x), "f"(v.y), "f"(v.z), "f"(v.w)
                 : "memory");

    if (sub == 0)
        atomicAdd(g_deg + d, 1.0f);
}

// ---------------------------------------------------------------------------
// Kernel 3: out = relu(agg/max(deg,1) + b), in place, float4-vectorized.
// ---------------------------------------------------------------------------
__global__ void __launch_bounds__(256) finalize_kernel(
        float* __restrict__ out,
        const float* __restrict__ b) {
    int t = blockIdx.x * blockDim.x + threadIdx.x;   // float4 index
    if (t >= N_NODES * OUT_FEATS / 4) return;
    int n  = t >> 3;   // node
    int j4 = t & 7;    // float4 within row

    float  deg  = __ldg(g_deg + n);
    float  norm = 1.0f / fmaxf(deg, 1.0f);
    float4 bb   = __ldg(reinterpret_cast<const float4*>(b) + j4);

    float4* out4 = reinterpret_cast<float4*>(out);
    float4 v = out4[t];
    v.x = fmaxf(fmaf(v.x, norm, bb.x), 0.0f);
    v.y = fmaxf(fmaf(v.y, norm, bb.y), 0.0f);
    v.z = fmaxf(fmaf(v.z, norm, bb.z), 0.0f);
    v.w = fmaxf(fmaf(v.w, norm, bb.w), 0.0f);
    out4[t] = v;
}

// ---------------------------------------------------------------------------
// Launch
// ---------------------------------------------------------------------------
extern "C" void kernel_launch(void* const* d_in, const int* in_sizes, int n_in,
                              void* d_out, int out_size) {
    const float* h     = (const float*)d_in[0];
    const int*   src   = (const int*)  d_in[1];
    const int*   dst   = (const int*)  d_in[2];
    const float* order = (const float*)d_in[3];
    const float* W     = (const float*)d_in[4];
    const float* b     = (const float*)d_in[5];
    float*       out   = (float*)d_out;

    (void)in_sizes; (void)n_in; (void)out_size;

    {
        long long total = (long long)NODE_PAIRS * 4;   // 200K threads
        int blocks = (int)((total + 255) / 256);
        gemm_zero_kernel<<<blocks, 256>>>(h, W, out);
    }

    {
        long long total = (long long)N_EDGES * 8;
        int blocks = (int)((total + 255) / 256);
        scatter_kernel<<<blocks, 256>>>(src, dst, order, out);
    }

    finalize_kernel<<<(N_NODES * OUT_FEATS / 4 + 255) / 256, 256>>>(out, b);
}

// round 8
// speedup vs baseline: 1.8508x; 1.8508x over previous
#include <cuda_runtime.h>
#include <cstdint>

#define N_NODES   100000
#define N_EDGES   1600000
#define IN_FEATS  64
#define OUT_FEATS 32
#define NODE_PAIRS (N_NODES / 2)

// Scratch (no cudaMalloc allowed)
__device__ float g_hW[N_NODES * OUT_FEATS];   // 12.8 MB
__device__ float g_deg[N_NODES];              // 0.4 MB

// ---------------------------------------------------------------------------
// Kernel 1: fused  (a) zero d_out + g_deg,  (b) hW = h @ W
// Round-5 body (2-node x 8-feature register tile, scalar FFMA + LDS.128),
// occupancy-tuned: 128-thread blocks, forced 12 blocks/SM (42 regs),
// explicit h prefetch to keep an LDG in flight.
// ---------------------------------------------------------------------------
__global__ void __launch_bounds__(128, 12) gemm_zero_kernel(
        const float* __restrict__ h,
        const float* __restrict__ W,
        float*       __restrict__ out) {
    __shared__ float4 sW4[IN_FEATS * OUT_FEATS / 4];   // 8 KB, natural [k][j]

    // stage W
    {
        const float4* W4 = reinterpret_cast<const float4*>(W);
        for (int i = threadIdx.x; i < IN_FEATS * OUT_FEATS / 4; i += blockDim.x)
            sW4[i] = W4[i];
    }

    // grid-stride zero of out (float4) and g_deg
    {
        int tg     = blockIdx.x * blockDim.x + threadIdx.x;
        int stride = gridDim.x * blockDim.x;
        float4 z = make_float4(0.f, 0.f, 0.f, 0.f);
        float4* out4 = reinterpret_cast<float4*>(out);
        for (int i = tg; i < N_NODES * OUT_FEATS / 4; i += stride)
            out4[i] = z;
        for (int i = tg; i < N_NODES; i += stride)
            g_deg[i] = 0.0f;
    }
    __syncthreads();

    int t  = blockIdx.x * blockDim.x + threadIdx.x;
    int np = t >> 2;            // node pair
    int jg = t & 3;             // 8-feature group
    if (np >= NODE_PAIRS) return;

    int node0 = np * 2;
    const float4* h0 = reinterpret_cast<const float4*>(h + (size_t)node0 * IN_FEATS);
    const float4* h1 = reinterpret_cast<const float4*>(h + (size_t)(node0 + 1) * IN_FEATS);

    float acc[2][8];
    #pragma unroll
    for (int i = 0; i < 2; i++)
        #pragma unroll
        for (int j = 0; j < 8; j++) acc[i][j] = 0.0f;

    // prefetch first k4
    float4 hv0 = __ldg(h0);
    float4 hv1 = __ldg(h1);

    #pragma unroll
    for (int k4 = 0; k4 < IN_FEATS / 4; k4++) {
        float4 cur0 = hv0, cur1 = hv1;
        if (k4 + 1 < IN_FEATS / 4) {
            hv0 = __ldg(h0 + k4 + 1);
            hv1 = __ldg(h1 + k4 + 1);
        }

        #pragma unroll
        for (int kk = 0; kk < 4; kk++) {
            int k = k4 * 4 + kk;
            float4 w0 = sW4[k * (OUT_FEATS / 4) + jg * 2 + 0];
            float4 w1 = sW4[k * (OUT_FEATS / 4) + jg * 2 + 1];
            float hk0 = (kk == 0) ? cur0.x : (kk == 1) ? cur0.y
                      : (kk == 2) ? cur0.z : cur0.w;
            float hk1 = (kk == 0) ? cur1.x : (kk == 1) ? cur1.y
                      : (kk == 2) ? cur1.z : cur1.w;

            acc[0][0] = fmaf(hk0, w0.x, acc[0][0]);
            acc[0][1] = fmaf(hk0, w0.y, acc[0][1]);
            acc[0][2] = fmaf(hk0, w0.z, acc[0][2]);
            acc[0][3] = fmaf(hk0, w0.w, acc[0][3]);
            acc[0][4] = fmaf(hk0, w1.x, acc[0][4]);
            acc[0][5] = fmaf(hk0, w1.y, acc[0][5]);
            acc[0][6] = fmaf(hk0, w1.z, acc[0][6]);
            acc[0][7] = fmaf(hk0, w1.w, acc[0][7]);

            acc[1][0] = fmaf(hk1, w0.x, acc[1][0]);
            acc[1][1] = fmaf(hk1, w0.y, acc[1][1]);
            acc[1][2] = fmaf(hk1, w0.z, acc[1][2]);
            acc[1][3] = fmaf(hk1, w0.w, acc[1][3]);
            acc[1][4] = fmaf(hk1, w1.x, acc[1][4]);
            acc[1][5] = fmaf(hk1, w1.y, acc[1][5]);
            acc[1][6] = fmaf(hk1, w1.z, acc[1][6]);
            acc[1][7] = fmaf(hk1, w1.w, acc[1][7]);
        }
    }

    #pragma unroll
    for (int i = 0; i < 2; i++) {
        float4* orow = reinterpret_cast<float4*>(
            g_hW + (size_t)(node0 + i) * OUT_FEATS + jg * 8);
        orow[0] = make_float4(acc[i][0], acc[i][1], acc[i][2], acc[i][3]);
        orow[1] = make_float4(acc[i][4], acc[i][5], acc[i][6], acc[i][7]);
    }
}

// ---------------------------------------------------------------------------
// Kernel 2: edge scatter. 8 threads per edge, one red.global.add.v4.f32 each.
// ---------------------------------------------------------------------------
__global__ void __launch_bounds__(256) scatter_kernel(
        const int*   __restrict__ src,
        const int*   __restrict__ dst,
        const float* __restrict__ order,
        float*       __restrict__ agg) {
    int t   = blockIdx.x * blockDim.x + threadIdx.x;
    int e   = t >> 3;
    int sub = t & 7;
    if (e >= N_EDGES) return;

    int   s = __ldg(src + e);
    int   d = __ldg(dst + e);
    float w = __ldg(order + e);

    float4 v = __ldg(reinterpret_cast<const float4*>(
                         g_hW + (size_t)s * OUT_FEATS + sub * 4));
    v.x *= w; v.y *= w; v.z *= w; v.w *= w;

    float* a = agg + (size_t)d * OUT_FEATS + sub * 4;
    asm volatile("red.global.add.v4.f32 [%0], {%1, %2, %3, %4};"
                 :: "l"(a), "f"(v.x), "f"(v.y), "f"(v.z), "f"(v.w)
                 : "memory");

    if (sub == 0)
        atomicAdd(g_deg + d, 1.0f);
}

// ---------------------------------------------------------------------------
// Kernel 3: out = relu(agg/max(deg,1) + b), in place, float4-vectorized.
// ---------------------------------------------------------------------------
__global__ void __launch_bounds__(256) finalize_kernel(
        float* __restrict__ out,
        const float* __restrict__ b) {
    int t = blockIdx.x * blockDim.x + threadIdx.x;   // float4 index
    if (t >= N_NODES * OUT_FEATS / 4) return;
    int n  = t >> 3;   // node
    int j4 = t & 7;    // float4 within row

    float  deg  = __ldg(g_deg + n);
    float  norm = 1.0f / fmaxf(deg, 1.0f);
    float4 bb   = __ldg(reinterpret_cast<const float4*>(b) + j4);

    float4* out4 = reinterpret_cast<float4*>(out);
    float4 v = out4[t];
    v.x = fmaxf(fmaf(v.x, norm, bb.x), 0.0f);
    v.y = fmaxf(fmaf(v.y, norm, bb.y), 0.0f);
    v.z = fmaxf(fmaf(v.z, norm, bb.z), 0.0f);
    v.w = fmaxf(fmaf(v.w, norm, bb.w), 0.0f);
    out4[t] = v;
}

// ---------------------------------------------------------------------------
// Launch
// ---------------------------------------------------------------------------
extern "C" void kernel_launch(void* const* d_in, const int* in_sizes, int n_in,
                              void* d_out, int out_size) {
    const float* h     = (const float*)d_in[0];
    const int*   src   = (const int*)  d_in[1];
    const int*   dst   = (const int*)  d_in[2];
    const float* order = (const float*)d_in[3];
    const float* W     = (const float*)d_in[4];
    const float* b     = (const float*)d_in[5];
    float*       out   = (float*)d_out;

    (void)in_sizes; (void)n_in; (void)out_size;

    {
        long long total = (long long)NODE_PAIRS * 4;   // 200K threads
        int blocks = (int)((total + 127) / 128);       // 128-thread blocks
        gemm_zero_kernel<<<blocks, 128>>>(h, W, out);
    }

    {
        long long total = (long long)N_EDGES * 8;
        int blocks = (int)((total + 255) / 256);
        scatter_kernel<<<blocks, 256>>>(src, dst, order, out);
    }

    finalize_kernel<<<(N_NODES * OUT_FEATS / 4 + 255) / 256, 256>>>(out, b);
}